// round 16
// baseline (speedup 1.0000x reference)
#include <cuda_runtime.h>
#include <cuda_fp16.h>
#include <math.h>

// Problem constants
#define B_   4
#define T_   2048
#define C_   1024
#define H_   16
#define D_   64
#define M_   (B_ * T_)        // 8192
#define C3_  (3 * C_)         // 3072

// ---------------------------------------------------------------------------
// Device scratch (no cudaMalloc allowed)
// ---------------------------------------------------------------------------
__device__ __align__(1024) __half g_xp[M_ * C_];       // x fp16 quad-permuted
__device__ __align__(1024) __half g_yp[M_ * C_];       // y fp16 quad-permuted
__device__ __align__(1024) __half g_wap[C3_ * C_];     // W_attn^T fp16 quad
__device__ __align__(1024) __half g_wpp[C_ * C_];      // W_proj^T fp16 quad
__device__ __align__(1024) __half g_qh[M_ * C_];       // Q (pre-scaled 1/64) fp16 quad
__device__ __align__(1024) __half g_kh[M_ * C_];       // K fp16 quad
__device__ __align__(1024) __half g_vt[B_ * H_ * D_ * T_];  // V^T [bh*64+d][T] fp16 quad

// ---------------------------------------------------------------------------
// Helpers
// ---------------------------------------------------------------------------
__device__ __forceinline__ unsigned smem_to_u32(const void* p) {
    unsigned a;
    asm("{ .reg .u64 t; cvta.to.shared.u64 t, %1; cvt.u32.u64 %0, t; }"
        : "=r"(a) : "l"(p));
    return a;
}

#define CP_ASYNC16(dst, src) \
    asm volatile("cp.async.cg.shared.global [%0], [%1], 16;" \
                 :: "r"(dst), "l"(src) : "memory")

__device__ __forceinline__ void mma_f16(float* c,
                                        unsigned a0, unsigned a1,
                                        unsigned a2, unsigned a3,
                                        unsigned b0, unsigned b1) {
    asm volatile(
        "mma.sync.aligned.m16n8k16.row.col.f32.f16.f16.f32 "
        "{%0,%1,%2,%3}, {%4,%5,%6,%7}, {%8,%9}, {%0,%1,%2,%3};"
        : "+f"(c[0]), "+f"(c[1]), "+f"(c[2]), "+f"(c[3])
        : "r"(a0), "r"(a1), "r"(a2), "r"(a3), "r"(b0), "r"(b1));
}

__device__ __forceinline__ unsigned h2u(float x, float y) {
    __half2 h = __floats2half2_rn(x, y);
    return *reinterpret_cast<unsigned*>(&h);
}

// Quad-permuted fp16 layout: within each 128B unit (two 32-half blocks),
// quad position = ((j&1)*4+t) ^ ((r&1)*4).
__device__ __forceinline__ size_t quad_off2(int r, int j, int t, int K) {
    return (size_t)r * (K * 2) + (size_t)(j >> 1) * 128
         + (((((j & 1) << 2) | t) ^ ((r & 1) << 2)) << 4);
}

// byte offset of half at (row, col) in a [rows][1024] quad matrix (col even)
__device__ __forceinline__ size_t qk_off(int row, int col) {
    int j = col >> 5, kk = col & 31;
    return (size_t)row * 2048 + (size_t)(j >> 1) * 128
         + (size_t)(((((((j & 1) << 2) | ((kk >> 1) & 3)) ^ ((row & 1) << 2)) << 4)
         + (((kk >> 4) & 1) << 3) + (((kk >> 3) & 1) << 2)));
}

// byte offset of half at (d-row = bhd, key) in V^T [bhd][2048] quad matrix
__device__ __forceinline__ size_t vt_off(int bhd, int d, int key) {
    int j = key >> 5, kk = key & 31;
    return (size_t)bhd * 4096 + (size_t)(key >> 6) * 128
         + (size_t)(((((((j & 1) << 2) | ((kk >> 1) & 3)) ^ ((d & 1) << 2)) << 4)
         + (((kk >> 4) & 1) << 3) + (((kk >> 3) & 1) << 2) + ((kk & 1) << 1)));
}

// ---------------------------------------------------------------------------
// Fused prep (high-MLP version):
//   blocks [0, XB2)        : xprep — one thread builds one 128B unit
//   blocks [XB2, +WAB2)    : W_attn^T prep — two quads per thread
//   blocks [.., PREP_TOT2) : W_proj^T prep — two quads per thread
// ---------------------------------------------------------------------------
#define PREP_XB2  ((M_ * 16) / 256)                    // 512  (16 units/row)
#define PREP_WAB2 ((C3_ / 256) * (C_ / 16))            // 768
#define PREP_WPB2 ((C_ / 256) * (C_ / 16))             // 256
#define PREP_TOT2 (PREP_XB2 + PREP_WAB2 + PREP_WPB2)   // 1536

// constant-index access into a float4[16] register array
#define AF(f, e) ((e & 3) == 0 ? f[(e) >> 2].x : \
                  (e & 3) == 1 ? f[(e) >> 2].y : \
                  (e & 3) == 2 ? f[(e) >> 2].z : f[(e) >> 2].w)

__device__ __forceinline__ void do_xprep_unit(const float* __restrict__ x,
                                              __half* __restrict__ xp,
                                              int blk) {
    int id = blk * 256 + threadIdx.x;      // 0..131071
    int r = id >> 4;                       // row
    int u = id & 15;                       // 128B unit within row
    const float4* src = reinterpret_cast<const float4*>(
        x + (size_t)r * C_ + u * 64);
    float4 f[16];
#pragma unroll
    for (int i = 0; i < 16; i++) f[i] = __ldcs(src + i);

    char* unit = reinterpret_cast<char*>(xp) + (size_t)r * 2048 + u * 128;
    const unsigned xr = (r & 1) << 2;
#pragma unroll
    for (int jj = 0; jj < 2; jj++)
#pragma unroll
        for (int t = 0; t < 4; t++) {
            uint4 w;
            w.x = h2u(AF(f, jj * 32 + 2 * t),      AF(f, jj * 32 + 2 * t + 1));
            w.y = h2u(AF(f, jj * 32 + 2 * t + 8),  AF(f, jj * 32 + 2 * t + 9));
            w.z = h2u(AF(f, jj * 32 + 2 * t + 16), AF(f, jj * 32 + 2 * t + 17));
            w.w = h2u(AF(f, jj * 32 + 2 * t + 24), AF(f, jj * 32 + 2 * t + 25));
            *reinterpret_cast<uint4*>(
                unit + (((unsigned)(jj * 4 + t) ^ xr) << 4)) = w;
        }
}

__device__ __forceinline__ void do_wtprep2(const float* __restrict__ W,
                                           __half* __restrict__ Wp,
                                           int bx, int by, int K, int N) {
    int n = bx * 256 + threadIdx.x;
    // two quads qA = 2*by, qB = 2*by+1 -> 16 independent coalesced loads
    int qA = 2 * by, qB = qA + 1;
    int jA = qA >> 2, tA = qA & 3;
    int jB = qB >> 2, tB = qB & 3;
    int ka = jA * 32 + 2 * tA;
    int kb = jB * 32 + 2 * tB;
    float a0 = W[(size_t)(ka + 0) * N + n],  a1 = W[(size_t)(ka + 1) * N + n];
    float a2 = W[(size_t)(ka + 8) * N + n],  a3 = W[(size_t)(ka + 9) * N + n];
    float a4 = W[(size_t)(ka + 16) * N + n], a5 = W[(size_t)(ka + 17) * N + n];
    float a6 = W[(size_t)(ka + 24) * N + n], a7 = W[(size_t)(ka + 25) * N + n];
    float b0 = W[(size_t)(kb + 0) * N + n],  b1 = W[(size_t)(kb + 1) * N + n];
    float b2 = W[(size_t)(kb + 8) * N + n],  b3 = W[(size_t)(kb + 9) * N + n];
    float b4 = W[(size_t)(kb + 16) * N + n], b5 = W[(size_t)(kb + 17) * N + n];
    float b6 = W[(size_t)(kb + 24) * N + n], b7 = W[(size_t)(kb + 25) * N + n];
    uint4 ua, ub;
    ua.x = h2u(a0, a1); ua.y = h2u(a2, a3); ua.z = h2u(a4, a5); ua.w = h2u(a6, a7);
    ub.x = h2u(b0, b1); ub.y = h2u(b2, b3); ub.z = h2u(b4, b5); ub.w = h2u(b6, b7);
    *reinterpret_cast<uint4*>(reinterpret_cast<char*>(Wp) + quad_off2(n, jA, tA, K)) = ua;
    *reinterpret_cast<uint4*>(reinterpret_cast<char*>(Wp) + quad_off2(n, jB, tB, K)) = ub;
}

__global__ void __launch_bounds__(256)
prep_fused_kernel(const float* __restrict__ x,
                  const float* __restrict__ W_attn,
                  const float* __restrict__ W_proj,
                  __half* __restrict__ xp,
                  __half* __restrict__ wap,
                  __half* __restrict__ wpp) {
    int blk = blockIdx.x;
    if (blk < PREP_XB2) {
        do_xprep_unit(x, xp, blk);
    } else if (blk < PREP_XB2 + PREP_WAB2) {
        int b = blk - PREP_XB2;
        int bx = b % (C3_ / 256);      // 12
        int by = b / (C3_ / 256);      // 64 (2 quads each)
        do_wtprep2(W_attn, wap, bx, by, C_, C3_);
    } else {
        int b = blk - PREP_XB2 - PREP_WAB2;
        int bx = b % (C_ / 256);       // 4
        int by = b / (C_ / 256);       // 64
        do_wtprep2(W_proj, wpp, bx, by, C_, C_);
    }
}

// ---------------------------------------------------------------------------
// fp16 tensor-core GEMM on quad-permuted operands (R14 winner, unchanged).
// ---------------------------------------------------------------------------
#define FSTAGES 3
#define F_A_BYTES (128 * 128)
#define F_STAGE_BYTES (2 * F_A_BYTES)
#define FSMEM_BYTES (FSTAGES * F_STAGE_BYTES)   // 96KB

__global__ void __launch_bounds__(128, 2)
gemm_f16_kernel(const __half* __restrict__ A, const __half* __restrict__ Bm,
                float* __restrict__ Cm, int M, int N, int K, int mode,
                __half* __restrict__ qh, __half* __restrict__ kh,
                __half* __restrict__ vt) {
    extern __shared__ __align__(16) char smc[];
    const unsigned sbase = smem_to_u32(smc);

    const int tid = threadIdx.x;
    const int wid = tid >> 5;
    const int lane = tid & 31;
    const int g = lane >> 2;
    const int t = lane & 3;
    const int warp_m = wid & 1;
    const int warp_n = wid >> 1;
    const int m0 = blockIdx.y * 128;
    const int n0 = blockIdx.x * 128;
    const int nchunks = K >> 6;
    const size_t K2 = (size_t)K * 2;

    const char* Ab = reinterpret_cast<const char*>(A);
    const char* Bb = reinterpret_cast<const char*>(Bm);

    float acc[4][8][4];
#pragma unroll
    for (int i = 0; i < 4; i++)
#pragma unroll
        for (int j = 0; j < 8; j++)
#pragma unroll
            for (int r = 0; r < 4; r++) acc[i][j][r] = 0.0f;

    auto issue = [&](int chunk) {
        const unsigned st = sbase + (unsigned)((chunk % FSTAGES) * F_STAGE_BYTES);
#pragma unroll
        for (int i = 0; i < 8; i++) {
            int idx = i * 128 + tid;
            int row = idx >> 3;
            int u = idx & 7;
            CP_ASYNC16(st + row * 128 + u * 16,
                       Ab + (size_t)(m0 + row) * K2 + (size_t)chunk * 128 + u * 16);
        }
        const unsigned stb = st + F_A_BYTES;
#pragma unroll
        for (int i = 0; i < 8; i++) {
            int idx = i * 128 + tid;
            int row = idx >> 3;
            int u = idx & 7;
            CP_ASYNC16(stb + row * 128 + u * 16,
                       Bb + (size_t)(n0 + row) * K2 + (size_t)chunk * 128 + u * 16);
        }
        asm volatile("cp.async.commit_group;" ::: "memory");
    };

    issue(0);
    issue(1);

    const unsigned xr = (g & 1) << 2;
    const int rowA0 = warp_m * 64 + g;
    const int rowB0 = warp_n * 64 + g;

    for (int c = 0; c < nchunks; c++) {
        if (c < nchunks - 1)
            asm volatile("cp.async.wait_group 1;" ::: "memory");
        else
            asm volatile("cp.async.wait_group 0;" ::: "memory");
        __syncthreads();

        if (c + 2 < nchunks) issue(c + 2);

        const char* As = smc + (c % FSTAGES) * F_STAGE_BYTES;
        const char* Bs = As + F_A_BYTES;

#pragma unroll
        for (int jb = 0; jb < 2; jb++) {
            const unsigned qoff = ((((unsigned)jb << 2) | (unsigned)t) ^ xr) << 4;
            uint4 qa[4][2], qb[8];
#pragma unroll
            for (int mt = 0; mt < 4; mt++) {
                qa[mt][0] = *reinterpret_cast<const uint4*>(
                    As + (rowA0 + mt * 16) * 128 + qoff);
                qa[mt][1] = *reinterpret_cast<const uint4*>(
                    As + (rowA0 + mt * 16 + 8) * 128 + qoff);
            }
#pragma unroll
            for (int nt = 0; nt < 8; nt++)
                qb[nt] = *reinterpret_cast<const uint4*>(
                    Bs + (rowB0 + nt * 8) * 128 + qoff);

#pragma unroll
            for (int mt = 0; mt < 4; mt++)
#pragma unroll
                for (int nt = 0; nt < 8; nt++)
                    mma_f16(acc[mt][nt],
                            qa[mt][0].x, qa[mt][1].x, qa[mt][0].y, qa[mt][1].y,
                            qb[nt].x, qb[nt].y);
#pragma unroll
            for (int mt = 0; mt < 4; mt++)
#pragma unroll
                for (int nt = 0; nt < 8; nt++)
                    mma_f16(acc[mt][nt],
                            qa[mt][0].z, qa[mt][1].z, qa[mt][0].w, qa[mt][1].w,
                            qb[nt].z, qb[nt].w);
        }
    }

    if (mode == 0) {
#pragma unroll
        for (int mt = 0; mt < 4; mt++) {
            int row0 = m0 + warp_m * 64 + mt * 16 + g;
#pragma unroll
            for (int nt = 0; nt < 8; nt++) {
                int col = n0 + warp_n * 64 + nt * 8 + 2 * t;
                *reinterpret_cast<float2*>(Cm + (size_t)row0 * N + col) =
                    make_float2(acc[mt][nt][0], acc[mt][nt][1]);
                *reinterpret_cast<float2*>(Cm + (size_t)(row0 + 8) * N + col) =
                    make_float2(acc[mt][nt][2], acc[mt][nt][3]);
            }
        }
        return;
    }

    // QKV epilogue: write fp16 quad-permuted Q / K / V^T
    const int region = n0 >> 10;    // 0=Q, 1=K, 2=V
    if (region <= 1) {
        char* dst = reinterpret_cast<char*>(region ? kh : qh);
        const int cb = n0 - region * 1024;
        const float sc = region ? 1.0f : (1.0f / (float)D_);
#pragma unroll
        for (int mt = 0; mt < 4; mt++) {
            int row0 = m0 + warp_m * 64 + mt * 16 + g;
#pragma unroll
            for (int nt = 0; nt < 8; nt++) {
                int col = cb + warp_n * 64 + nt * 8 + 2 * t;
                size_t off = qk_off(row0, col);
                __half2 h0 = __floats2half2_rn(acc[mt][nt][0] * sc, acc[mt][nt][1] * sc);
                __half2 h1 = __floats2half2_rn(acc[mt][nt][2] * sc, acc[mt][nt][3] * sc);
                *reinterpret_cast<__half2*>(dst + off) = h0;
                *reinterpret_cast<__half2*>(dst + off + 8 * 2048) = h1;
            }
        }
    } else {
        char* dst = reinterpret_cast<char*>(vt);
#pragma unroll
        for (int mt = 0; mt < 4; mt++) {
            int row0 = m0 + warp_m * 64 + mt * 16 + g;
            int b = row0 >> 11;
            int key = row0 & (T_ - 1);
#pragma unroll
            for (int nt = 0; nt < 8; nt++) {
                int col2 = (n0 - 2048) + warp_n * 64 + nt * 8 + 2 * t;
                int d = col2 & 63;
                int hh = col2 >> 6;
                int bhd = (b * H_ + hh) * 64 + d;
                *reinterpret_cast<__half*>(dst + vt_off(bhd, d, key)) =
                    __float2half_rn(acc[mt][nt][0]);
                *reinterpret_cast<__half*>(dst + vt_off(bhd + 1, d + 1, key)) =
                    __float2half_rn(acc[mt][nt][1]);
                *reinterpret_cast<__half*>(dst + vt_off(bhd, d, key + 8)) =
                    __float2half_rn(acc[mt][nt][2]);
                *reinterpret_cast<__half*>(dst + vt_off(bhd + 1, d + 1, key + 8)) =
                    __float2half_rn(acc[mt][nt][3]);
            }
        }
    }
}

// ---------------------------------------------------------------------------
// Diagonal-tile helper with compile-time bounds (R14 winner, unchanged).
// ---------------------------------------------------------------------------
template <int NTMAX, int C2MAX>
__device__ __forceinline__ void diag_tile(
    const char* Ks, const char* Vs, int k0, int qr0,
    const uint4 (&qa)[2][2], unsigned xr, int g, int t,
    float (&o)[8][4], float& lsum0, float& lsum1) {
    float sf[NTMAX][4];
#pragma unroll
    for (int nt = 0; nt < NTMAX; nt++)
#pragma unroll
        for (int r = 0; r < 4; r++) sf[nt][r] = 0.0f;

#pragma unroll
    for (int j = 0; j < 2; j++) {
        const unsigned qoff = ((((unsigned)(j << 2)) | (unsigned)t) ^ xr) << 4;
        uint4 kb[NTMAX];
#pragma unroll
        for (int nt = 0; nt < NTMAX; nt++)
            kb[nt] = *reinterpret_cast<const uint4*>(Ks + (nt * 8 + g) * 128 + qoff);
#pragma unroll
        for (int nt = 0; nt < NTMAX; nt++)
            mma_f16(sf[nt],
                    qa[j][0].x, qa[j][1].x, qa[j][0].y, qa[j][1].y,
                    kb[nt].x, kb[nt].y);
#pragma unroll
        for (int nt = 0; nt < NTMAX; nt++)
            mma_f16(sf[nt],
                    qa[j][0].z, qa[j][1].z, qa[j][0].w, qa[j][1].w,
                    kb[nt].z, kb[nt].w);
    }

    const int qr1 = qr0 + 8;
#pragma unroll
    for (int nt = 0; nt < NTMAX; nt++) {
        int kc = k0 + nt * 8 + 2 * t;
        if (kc > qr0)     sf[nt][0] = -1e30f;
        if (kc + 1 > qr0) sf[nt][1] = -1e30f;
        if (kc > qr1)     sf[nt][2] = -1e30f;
        if (kc + 1 > qr1) sf[nt][3] = -1e30f;
        sf[nt][0] = __expf(sf[nt][0]);
        sf[nt][1] = __expf(sf[nt][1]);
        sf[nt][2] = __expf(sf[nt][2]);
        sf[nt][3] = __expf(sf[nt][3]);
        lsum0 += sf[nt][0] + sf[nt][1];
        lsum1 += sf[nt][2] + sf[nt][3];
    }

#pragma unroll
    for (int j = 0; j < 2; j++) {
        if (2 * j < C2MAX) {
            const unsigned qoff = ((((unsigned)(j << 2)) | (unsigned)t) ^ xr) << 4;
            uint4 vb[8];
#pragma unroll
            for (int nt = 0; nt < 8; nt++)
                vb[nt] = *reinterpret_cast<const uint4*>(Vs + (nt * 8 + g) * 128 + qoff);
#pragma unroll
            for (int s2 = 0; s2 < 2; s2++) {
                if (2 * j + s2 < C2MAX) {
                    const int np = j * 4 + s2 * 2;
                    unsigned a0 = h2u(sf[np][0],     sf[np][1]);
                    unsigned a1 = h2u(sf[np][2],     sf[np][3]);
                    unsigned a2 = h2u(sf[np + 1][0], sf[np + 1][1]);
                    unsigned a3 = h2u(sf[np + 1][2], sf[np + 1][3]);
#pragma unroll
                    for (int nt = 0; nt < 8; nt++)
                        mma_f16(o[nt], a0, a1, a2, a3,
                                s2 ? vb[nt].z : vb[nt].x,
                                s2 ? vb[nt].w : vb[nt].y);
                }
            }
        }
    }
}

// ---------------------------------------------------------------------------
// fp16 tensor-core flash attention (R14 winner, unchanged): max-free softmax,
// clean main loop, peeled compile-time diagonal tile.
// ---------------------------------------------------------------------------
#define AST_K_BYTES (64 * 128)
#define AST_STAGE (2 * AST_K_BYTES)          // 16KB
#define ATTN_SMEM (2 * AST_STAGE)            // 32KB

__global__ void __launch_bounds__(128, 3)
attn_f16_kernel(const __half* __restrict__ qhg, const __half* __restrict__ khg,
                const __half* __restrict__ vtg, __half* __restrict__ yp) {
    extern __shared__ __align__(16) char smb[];
    const unsigned sbase = smem_to_u32(smb);

    const int tid = threadIdx.x;
    const int wid = tid >> 5;
    const int lane = tid & 31;
    const int g = lane >> 2;
    const int t = lane & 3;
    const int qi = (gridDim.x - 1) - blockIdx.x;   // heavy tiles first
    const int h = blockIdx.y;
    const int b = blockIdx.z;
    const int q0 = qi * 64;
    const size_t row_base = (size_t)b * T_;
    const int bh = b * H_ + h;
    const unsigned xr = (g & 1) << 2;

    uint4 qa[2][2];
#pragma unroll
    for (int j = 0; j < 2; j++) {
        const char* qp = reinterpret_cast<const char*>(qhg)
            + (row_base + q0 + wid * 16 + g) * 2048 + h * 128
            + ((((unsigned)(j << 2) | (unsigned)t) ^ xr) << 4);
        qa[j][0] = *reinterpret_cast<const uint4*>(qp);
        qa[j][1] = *reinterpret_cast<const uint4*>(qp + 8 * 2048);
    }

    float lsum0 = 0.0f, lsum1 = 0.0f;
    float o[8][4];
#pragma unroll
    for (int nt = 0; nt < 8; nt++)
#pragma unroll
        for (int r = 0; r < 4; r++) o[nt][r] = 0.0f;

    const char* khb = reinterpret_cast<const char*>(khg);
    const char* vtb = reinterpret_cast<const char*>(vtg);

    auto issue = [&](int kt) {
        const unsigned st = sbase + (unsigned)((kt & 1) * AST_STAGE);
        const int k0 = kt * 64;
#pragma unroll
        for (int i = 0; i < 4; i++) {
            int idx = i * 128 + tid;
            int kk = idx >> 3;
            int u = idx & 7;
            CP_ASYNC16(st + kk * 128 + u * 16,
                       khb + (row_base + k0 + kk) * 2048 + h * 128 + u * 16);
        }
#pragma unroll
        for (int i = 0; i < 4; i++) {
            int idx = i * 128 + tid;
            int d = idx >> 3;
            int u = idx & 7;
            CP_ASYNC16(st + AST_K_BYTES + d * 128 + u * 16,
                       vtb + (size_t)(bh * 64 + d) * 4096 + (size_t)kt * 128 + u * 16);
        }
        asm volatile("cp.async.commit_group;" ::: "memory");
    };

    issue(0);

    for (int kt = 0; kt < qi; kt++) {
        __syncthreads();
        issue(kt + 1);
        asm volatile("cp.async.wait_group 1;" ::: "memory");
        __syncthreads();

        const char* Ks = smb + (kt & 1) * AST_STAGE;
        const char* Vs = Ks + AST_K_BYTES;

        float sf[8][4];
#pragma unroll
        for (int nt = 0; nt < 8; nt++)
#pragma unroll
            for (int r = 0; r < 4; r++) sf[nt][r] = 0.0f;

#pragma unroll
        for (int j = 0; j < 2; j++) {
            const unsigned qoff = ((((unsigned)(j << 2)) | (unsigned)t) ^ xr) << 4;
            uint4 kb[8];
#pragma unroll
            for (int nt = 0; nt < 8; nt++)
                kb[nt] = *reinterpret_cast<const uint4*>(Ks + (nt * 8 + g) * 128 + qoff);
#pragma unroll
            for (int nt = 0; nt < 8; nt++)
                mma_f16(sf[nt],
                        qa[j][0].x, qa[j][1].x, qa[j][0].y, qa[j][1].y,
                        kb[nt].x, kb[nt].y);
#pragma unroll
            for (int nt = 0; nt < 8; nt++)
                mma_f16(sf[nt],
                        qa[j][0].z, qa[j][1].z, qa[j][0].w, qa[j][1].w,
                        kb[nt].z, kb[nt].w);
        }

#pragma unroll
        for (int nt = 0; nt < 8; nt++) {
            sf[nt][0] = __expf(sf[nt][0]);
            sf[nt][1] = __expf(sf[nt][1]);
            sf[nt][2] = __expf(sf[nt][2]);
            sf[nt][3] = __expf(sf[nt][3]);
            lsum0 += sf[nt][0] + sf[nt][1];
            lsum1 += sf[nt][2] + sf[nt][3];
        }

#pragma unroll
        for (int j = 0; j < 2; j++) {
            const unsigned qoff = ((((unsigned)(j << 2)) | (unsigned)t) ^ xr) << 4;
            uint4 vb[8];
#pragma unroll
            for (int nt = 0; nt < 8; nt++)
                vb[nt] = *reinterpret_cast<const uint4*>(Vs + (nt * 8 + g) * 128 + qoff);
#pragma unroll
            for (int s2 = 0; s2 < 2; s2++) {
                const int np = j * 4 + s2 * 2;
                unsigned a0 = h2u(sf[np][0],     sf[np][1]);
                unsigned a1 = h2u(sf[np][2],     sf[np][3]);
                unsigned a2 = h2u(sf[np + 1][0], sf[np + 1][1]);
                unsigned a3 = h2u(sf[np + 1][2], sf[np + 1][3]);
#pragma unroll
                for (int nt = 0; nt < 8; nt++)
                    mma_f16(o[nt], a0, a1, a2, a3,
                            s2 ? vb[nt].z : vb[nt].x,
                            s2 ? vb[nt].w : vb[nt].y);
            }
        }
    }

    // ---- Peeled diagonal tile ----
    {
        __syncthreads();
        asm volatile("cp.async.wait_group 0;" ::: "memory");
        __syncthreads();

        const char* Ks = smb + (qi & 1) * AST_STAGE;
        const char* Vs = Ks + AST_K_BYTES;
        const int k0 = qi * 64;
        const int qr0 = q0 + wid * 16 + g;

        switch (wid) {
        case 0: diag_tile<2, 1>(Ks, Vs, k0, qr0, qa, xr, g, t, o, lsum0, lsum1); break;
        case 1: diag_tile<4, 2>(Ks, Vs, k0, qr0, qa, xr, g, t, o, lsum0, lsum1); break;
        case 2: diag_tile<6, 3>(Ks, Vs, k0, qr0, qa, xr, g, t, o, lsum0, lsum1); break;
        default: diag_tile<8, 4>(Ks, Vs, k0, qr0, qa, xr, g, t, o, lsum0, lsum1); break;
        }
    }

    // ---- Epilogue ----
    lsum0 += __shfl_xor_sync(0xffffffffu, lsum0, 1);
    lsum0 += __shfl_xor_sync(0xffffffffu, lsum0, 2);
    lsum1 += __shfl_xor_sync(0xffffffffu, lsum1, 1);
    lsum1 += __shfl_xor_sync(0xffffffffu, lsum1, 2);
    const float il0 = 1.0f / lsum0;
    const float il1 = 1.0f / lsum1;

    char* ypc = reinterpret_cast<char*>(yp);
    const int hcol = h * D_;
    const int r0 = (int)(row_base + q0 + wid * 16 + g);
#pragma unroll
    for (int nt = 0; nt < 8; nt++) {
        const int col = hcol + nt * 8 + 2 * t;
        size_t off = qk_off(r0, col);
        __half2 hv0 = __floats2half2_rn(o[nt][0] * il0, o[nt][1] * il0);
        __half2 hv1 = __floats2half2_rn(o[nt][2] * il1, o[nt][3] * il1);
        *reinterpret_cast<__half2*>(ypc + off) = hv0;
        *reinterpret_cast<__half2*>(ypc + off + 8 * 2048) = hv1;
    }
}

// ---------------------------------------------------------------------------
// Launch
// ---------------------------------------------------------------------------
extern "C" void kernel_launch(void* const* d_in, const int* in_sizes, int n_in,
                              void* d_out, int out_size) {
    const float* x      = (const float*)d_in[0];   // [4,2048,1024]
    const float* W_attn = (const float*)d_in[1];   // [1024,3072]
    const float* W_proj = (const float*)d_in[2];   // [1024,1024]
    float* out = (float*)d_out;

    __half *xp, *yp, *wap, *wpp, *qh, *kh, *vt;
    cudaGetSymbolAddress((void**)&xp, g_xp);
    cudaGetSymbolAddress((void**)&yp, g_yp);
    cudaGetSymbolAddress((void**)&wap, g_wap);
    cudaGetSymbolAddress((void**)&wpp, g_wpp);
    cudaGetSymbolAddress((void**)&qh, g_qh);
    cudaGetSymbolAddress((void**)&kh, g_kh);
    cudaGetSymbolAddress((void**)&vt, g_vt);

    cudaFuncSetAttribute(gemm_f16_kernel,
                         cudaFuncAttributeMaxDynamicSharedMemorySize, FSMEM_BYTES);
    cudaFuncSetAttribute(attn_f16_kernel,
                         cudaFuncAttributeMaxDynamicSharedMemorySize, ATTN_SMEM);

    // 0) fused prep (high-MLP): x + both weights, one launch
    prep_fused_kernel<<<PREP_TOT2, 256>>>(x, W_attn, W_proj, xp, wap, wpp);

    // 1) qkv = x @ W_attn -> Q (scaled), K, V^T directly as fp16 quad
    gemm_f16_kernel<<<dim3(C3_ / 128, M_ / 128), 128, FSMEM_BYTES>>>(
        xp, wap, nullptr, M_, C3_, C_, 1, qh, kh, vt);

    // 2) causal attention (fp16 mma, max-free softmax, peeled diag tile)
    attn_f16_kernel<<<dim3(T_ / 64, H_, B_), 128, ATTN_SMEM>>>(qh, kh, vt, yp);

    // 3) out = y @ W_proj (fp32-accum, fp32 out)
    gemm_f16_kernel<<<dim3(C_ / 128, M_ / 128), 128, FSMEM_BYTES>>>(
        yp, wpp, out, M_, C_, C_, 0, nullptr, nullptr, nullptr);
}

// round 17
// speedup vs baseline: 1.0190x; 1.0190x over previous
#include <cuda_runtime.h>
#include <cuda_fp16.h>
#include <math.h>

// Problem constants
#define B_   4
#define T_   2048
#define C_   1024
#define H_   16
#define D_   64
#define M_   (B_ * T_)        // 8192
#define C3_  (3 * C_)         // 3072

// ---------------------------------------------------------------------------
// Device scratch (no cudaMalloc allowed)
// ---------------------------------------------------------------------------
__device__ __align__(1024) __half g_xp[M_ * C_];       // x fp16 quad-permuted
__device__ __align__(1024) __half g_yp[M_ * C_];       // y fp16 quad-permuted
__device__ __align__(1024) __half g_wap[C3_ * C_];     // W_attn^T fp16 quad
__device__ __align__(1024) __half g_wpp[C_ * C_];      // W_proj^T fp16 quad
__device__ __align__(1024) __half g_qh[M_ * C_];       // Q (pre-scaled 1/64) fp16 quad
__device__ __align__(1024) __half g_kh[M_ * C_];       // K fp16 quad
__device__ __align__(1024) __half g_vt[B_ * H_ * D_ * T_];  // V^T [bh*64+d][T] fp16 quad

// ---------------------------------------------------------------------------
// Helpers
// ---------------------------------------------------------------------------
__device__ __forceinline__ unsigned smem_to_u32(const void* p) {
    unsigned a;
    asm("{ .reg .u64 t; cvta.to.shared.u64 t, %1; cvt.u32.u64 %0, t; }"
        : "=r"(a) : "l"(p));
    return a;
}

#define CP_ASYNC16(dst, src) \
    asm volatile("cp.async.cg.shared.global [%0], [%1], 16;" \
                 :: "r"(dst), "l"(src) : "memory")

__device__ __forceinline__ void mma_f16(float* c,
                                        unsigned a0, unsigned a1,
                                        unsigned a2, unsigned a3,
                                        unsigned b0, unsigned b1) {
    asm volatile(
        "mma.sync.aligned.m16n8k16.row.col.f32.f16.f16.f32 "
        "{%0,%1,%2,%3}, {%4,%5,%6,%7}, {%8,%9}, {%0,%1,%2,%3};"
        : "+f"(c[0]), "+f"(c[1]), "+f"(c[2]), "+f"(c[3])
        : "r"(a0), "r"(a1), "r"(a2), "r"(a3), "r"(b0), "r"(b1));
}

__device__ __forceinline__ unsigned h2u(float x, float y) {
    __half2 h = __floats2half2_rn(x, y);
    return *reinterpret_cast<unsigned*>(&h);
}

// Quad-permuted fp16 layout: within each 128B unit (two 32-half blocks),
// quad position = ((j&1)*4+t) ^ ((r&1)*4).
__device__ __forceinline__ size_t quad_off2(int r, int j, int t, int K) {
    return (size_t)r * (K * 2) + (size_t)(j >> 1) * 128
         + (((((j & 1) << 2) | t) ^ ((r & 1) << 2)) << 4);
}

// byte offset of half at (row, col) in a [rows][1024] quad matrix (col even)
__device__ __forceinline__ size_t qk_off(int row, int col) {
    int j = col >> 5, kk = col & 31;
    return (size_t)row * 2048 + (size_t)(j >> 1) * 128
         + (size_t)(((((((j & 1) << 2) | ((kk >> 1) & 3)) ^ ((row & 1) << 2)) << 4)
         + (((kk >> 4) & 1) << 3) + (((kk >> 3) & 1) << 2)));
}

// byte offset of half at (d-row = bhd, key) in V^T [bhd][2048] quad matrix
__device__ __forceinline__ size_t vt_off(int bhd, int d, int key) {
    int j = key >> 5, kk = key & 31;
    return (size_t)bhd * 4096 + (size_t)(key >> 6) * 128
         + (size_t)(((((((j & 1) << 2) | ((kk >> 1) & 3)) ^ ((d & 1) << 2)) << 4)
         + (((kk >> 4) & 1) << 3) + (((kk >> 3) & 1) << 2) + ((kk & 1) << 1)));
}

// ---------------------------------------------------------------------------
// Fused prep (R14 version): x->xp, W_attn->wap, W_proj->wpp in one launch.
// ---------------------------------------------------------------------------
#define PREP_XB  ((M_ * C_ / 8) / 256)                 // 4096
#define PREP_WAB ((C3_ / 256) * (C_ / 8))              // 1536
#define PREP_WPB ((C_ / 256) * (C_ / 8))               // 512
#define PREP_TOTAL (PREP_XB + PREP_WAB + PREP_WPB)     // 6144

__device__ __forceinline__ void do_xprep(const float* __restrict__ x,
                                         __half* __restrict__ xp,
                                         int blk, int K) {
    int id = blk * 256 + threadIdx.x;
    int qpr = K >> 3;
    int r = id / qpr;
    int q = id - r * qpr;
    int j = q >> 2;
    int t = q & 3;
    const float* src = x + (size_t)r * K + j * 32 + 2 * t;
    float2 v0 = *reinterpret_cast<const float2*>(src);
    float2 v1 = *reinterpret_cast<const float2*>(src + 8);
    float2 v2 = *reinterpret_cast<const float2*>(src + 16);
    float2 v3 = *reinterpret_cast<const float2*>(src + 24);
    uint4 u;
    u.x = h2u(v0.x, v0.y);
    u.y = h2u(v1.x, v1.y);
    u.z = h2u(v2.x, v2.y);
    u.w = h2u(v3.x, v3.y);
    *reinterpret_cast<uint4*>(reinterpret_cast<char*>(xp) + quad_off2(r, j, t, K)) = u;
}

__device__ __forceinline__ void do_wtprep(const float* __restrict__ W,
                                          __half* __restrict__ Wp,
                                          int bx, int by, int K, int N) {
    int n = bx * 256 + threadIdx.x;
    int q = by;
    int j = q >> 2;
    int t = q & 3;
    int kb = j * 32 + 2 * t;
    uint4 u;
    u.x = h2u(W[(size_t)(kb + 0) * N + n],  W[(size_t)(kb + 1) * N + n]);
    u.y = h2u(W[(size_t)(kb + 8) * N + n],  W[(size_t)(kb + 9) * N + n]);
    u.z = h2u(W[(size_t)(kb + 16) * N + n], W[(size_t)(kb + 17) * N + n]);
    u.w = h2u(W[(size_t)(kb + 24) * N + n], W[(size_t)(kb + 25) * N + n]);
    *reinterpret_cast<uint4*>(reinterpret_cast<char*>(Wp) + quad_off2(n, j, t, K)) = u;
}

__global__ void __launch_bounds__(256)
prep_fused_kernel(const float* __restrict__ x,
                  const float* __restrict__ W_attn,
                  const float* __restrict__ W_proj,
                  __half* __restrict__ xp,
                  __half* __restrict__ wap,
                  __half* __restrict__ wpp) {
    int blk = blockIdx.x;
    if (blk < PREP_XB) {
        do_xprep(x, xp, blk, C_);
    } else if (blk < PREP_XB + PREP_WAB) {
        int b = blk - PREP_XB;
        int bx = b % (C3_ / 256);
        int by = b / (C3_ / 256);
        do_wtprep(W_attn, wap, bx, by, C_, C3_);
    } else {
        int b = blk - PREP_XB - PREP_WAB;
        int bx = b % (C_ / 256);
        int by = b / (C_ / 256);
        do_wtprep(W_proj, wpp, bx, by, C_, C_);
    }
}

// ---------------------------------------------------------------------------
// fp16 tensor-core GEMM on quad-permuted operands (R14 winner; final chunk
// peeled out of the hot loop).
// ---------------------------------------------------------------------------
#define FSTAGES 3
#define F_A_BYTES (128 * 128)
#define F_STAGE_BYTES (2 * F_A_BYTES)
#define FSMEM_BYTES (FSTAGES * F_STAGE_BYTES)   // 96KB

__global__ void __launch_bounds__(128, 2)
gemm_f16_kernel(const __half* __restrict__ A, const __half* __restrict__ Bm,
                float* __restrict__ Cm, int M, int N, int K, int mode,
                __half* __restrict__ qh, __half* __restrict__ kh,
                __half* __restrict__ vt) {
    extern __shared__ __align__(16) char smc[];
    const unsigned sbase = smem_to_u32(smc);

    const int tid = threadIdx.x;
    const int wid = tid >> 5;
    const int lane = tid & 31;
    const int g = lane >> 2;
    const int t = lane & 3;
    const int warp_m = wid & 1;
    const int warp_n = wid >> 1;
    const int m0 = blockIdx.y * 128;
    const int n0 = blockIdx.x * 128;
    const int nchunks = K >> 6;
    const size_t K2 = (size_t)K * 2;

    const char* Ab = reinterpret_cast<const char*>(A);
    const char* Bb = reinterpret_cast<const char*>(Bm);

    float acc[4][8][4];
#pragma unroll
    for (int i = 0; i < 4; i++)
#pragma unroll
        for (int j = 0; j < 8; j++)
#pragma unroll
            for (int r = 0; r < 4; r++) acc[i][j][r] = 0.0f;

    auto issue = [&](int chunk) {
        const unsigned st = sbase + (unsigned)((chunk % FSTAGES) * F_STAGE_BYTES);
#pragma unroll
        for (int i = 0; i < 8; i++) {
            int idx = i * 128 + tid;
            int row = idx >> 3;
            int u = idx & 7;
            CP_ASYNC16(st + row * 128 + u * 16,
                       Ab + (size_t)(m0 + row) * K2 + (size_t)chunk * 128 + u * 16);
        }
        const unsigned stb = st + F_A_BYTES;
#pragma unroll
        for (int i = 0; i < 8; i++) {
            int idx = i * 128 + tid;
            int row = idx >> 3;
            int u = idx & 7;
            CP_ASYNC16(stb + row * 128 + u * 16,
                       Bb + (size_t)(n0 + row) * K2 + (size_t)chunk * 128 + u * 16);
        }
        asm volatile("cp.async.commit_group;" ::: "memory");
    };

    const unsigned xr = (g & 1) << 2;
    const int rowA0 = warp_m * 64 + g;
    const int rowB0 = warp_n * 64 + g;

    // per-chunk compute body
    auto compute = [&](int c) {
        const char* As = smc + (c % FSTAGES) * F_STAGE_BYTES;
        const char* Bs = As + F_A_BYTES;
#pragma unroll
        for (int jb = 0; jb < 2; jb++) {
            const unsigned qoff = ((((unsigned)jb << 2) | (unsigned)t) ^ xr) << 4;
            uint4 qa[4][2], qb[8];
#pragma unroll
            for (int mt = 0; mt < 4; mt++) {
                qa[mt][0] = *reinterpret_cast<const uint4*>(
                    As + (rowA0 + mt * 16) * 128 + qoff);
                qa[mt][1] = *reinterpret_cast<const uint4*>(
                    As + (rowA0 + mt * 16 + 8) * 128 + qoff);
            }
#pragma unroll
            for (int nt = 0; nt < 8; nt++)
                qb[nt] = *reinterpret_cast<const uint4*>(
                    Bs + (rowB0 + nt * 8) * 128 + qoff);

#pragma unroll
            for (int mt = 0; mt < 4; mt++)
#pragma unroll
                for (int nt = 0; nt < 8; nt++)
                    mma_f16(acc[mt][nt],
                            qa[mt][0].x, qa[mt][1].x, qa[mt][0].y, qa[mt][1].y,
                            qb[nt].x, qb[nt].y);
#pragma unroll
            for (int mt = 0; mt < 4; mt++)
#pragma unroll
                for (int nt = 0; nt < 8; nt++)
                    mma_f16(acc[mt][nt],
                            qa[mt][0].z, qa[mt][1].z, qa[mt][0].w, qa[mt][1].w,
                            qb[nt].z, qb[nt].w);
        }
    };

    issue(0);
    issue(1);

    // hot loop: always has a next chunk to prefetch, no in-loop predicate
    for (int c = 0; c < nchunks - 1; c++) {
        asm volatile("cp.async.wait_group 1;" ::: "memory");
        __syncthreads();
        if (c + 2 < nchunks) issue(c + 2);
        compute(c);
        __syncthreads();
    }
    // peeled final chunk
    asm volatile("cp.async.wait_group 0;" ::: "memory");
    __syncthreads();
    compute(nchunks - 1);

    if (mode == 0) {
#pragma unroll
        for (int mt = 0; mt < 4; mt++) {
            int row0 = m0 + warp_m * 64 + mt * 16 + g;
#pragma unroll
            for (int nt = 0; nt < 8; nt++) {
                int col = n0 + warp_n * 64 + nt * 8 + 2 * t;
                *reinterpret_cast<float2*>(Cm + (size_t)row0 * N + col) =
                    make_float2(acc[mt][nt][0], acc[mt][nt][1]);
                *reinterpret_cast<float2*>(Cm + (size_t)(row0 + 8) * N + col) =
                    make_float2(acc[mt][nt][2], acc[mt][nt][3]);
            }
        }
        return;
    }

    // QKV epilogue: write fp16 quad-permuted Q / K / V^T
    const int region = n0 >> 10;    // 0=Q, 1=K, 2=V
    if (region <= 1) {
        char* dst = reinterpret_cast<char*>(region ? kh : qh);
        const int cb = n0 - region * 1024;
        const float sc = region ? 1.0f : (1.0f / (float)D_);
#pragma unroll
        for (int mt = 0; mt < 4; mt++) {
            int row0 = m0 + warp_m * 64 + mt * 16 + g;
#pragma unroll
            for (int nt = 0; nt < 8; nt++) {
                int col = cb + warp_n * 64 + nt * 8 + 2 * t;
                size_t off = qk_off(row0, col);
                __half2 h0 = __floats2half2_rn(acc[mt][nt][0] * sc, acc[mt][nt][1] * sc);
                __half2 h1 = __floats2half2_rn(acc[mt][nt][2] * sc, acc[mt][nt][3] * sc);
                *reinterpret_cast<__half2*>(dst + off) = h0;
                *reinterpret_cast<__half2*>(dst + off + 8 * 2048) = h1;
            }
        }
    } else {
        char* dst = reinterpret_cast<char*>(vt);
#pragma unroll
        for (int mt = 0; mt < 4; mt++) {
            int row0 = m0 + warp_m * 64 + mt * 16 + g;
            int b = row0 >> 11;
            int key = row0 & (T_ - 1);
#pragma unroll
            for (int nt = 0; nt < 8; nt++) {
                int col2 = (n0 - 2048) + warp_n * 64 + nt * 8 + 2 * t;
                int d = col2 & 63;
                int hh = col2 >> 6;
                int bhd = (b * H_ + hh) * 64 + d;
                *reinterpret_cast<__half*>(dst + vt_off(bhd, d, key)) =
                    __float2half_rn(acc[mt][nt][0]);
                *reinterpret_cast<__half*>(dst + vt_off(bhd + 1, d + 1, key)) =
                    __float2half_rn(acc[mt][nt][1]);
                *reinterpret_cast<__half*>(dst + vt_off(bhd, d, key + 8)) =
                    __float2half_rn(acc[mt][nt][2]);
                *reinterpret_cast<__half*>(dst + vt_off(bhd + 1, d + 1, key + 8)) =
                    __float2half_rn(acc[mt][nt][3]);
            }
        }
    }
}

// ---------------------------------------------------------------------------
// Diagonal-tile helper with compile-time bounds (R14 winner, unchanged).
// ---------------------------------------------------------------------------
template <int NTMAX, int C2MAX>
__device__ __forceinline__ void diag_tile(
    const char* Ks, const char* Vs, int k0, int qr0,
    const uint4 (&qa)[2][2], unsigned xr, int g, int t,
    float (&o)[8][4], float& lsum0, float& lsum1) {
    float sf[NTMAX][4];
#pragma unroll
    for (int nt = 0; nt < NTMAX; nt++)
#pragma unroll
        for (int r = 0; r < 4; r++) sf[nt][r] = 0.0f;

#pragma unroll
    for (int j = 0; j < 2; j++) {
        const unsigned qoff = ((((unsigned)(j << 2)) | (unsigned)t) ^ xr) << 4;
        uint4 kb[NTMAX];
#pragma unroll
        for (int nt = 0; nt < NTMAX; nt++)
            kb[nt] = *reinterpret_cast<const uint4*>(Ks + (nt * 8 + g) * 128 + qoff);
#pragma unroll
        for (int nt = 0; nt < NTMAX; nt++)
            mma_f16(sf[nt],
                    qa[j][0].x, qa[j][1].x, qa[j][0].y, qa[j][1].y,
                    kb[nt].x, kb[nt].y);
#pragma unroll
        for (int nt = 0; nt < NTMAX; nt++)
            mma_f16(sf[nt],
                    qa[j][0].z, qa[j][1].z, qa[j][0].w, qa[j][1].w,
                    kb[nt].z, kb[nt].w);
    }

    const int qr1 = qr0 + 8;
#pragma unroll
    for (int nt = 0; nt < NTMAX; nt++) {
        int kc = k0 + nt * 8 + 2 * t;
        if (kc > qr0)     sf[nt][0] = -1e30f;
        if (kc + 1 > qr0) sf[nt][1] = -1e30f;
        if (kc > qr1)     sf[nt][2] = -1e30f;
        if (kc + 1 > qr1) sf[nt][3] = -1e30f;
        sf[nt][0] = __expf(sf[nt][0]);
        sf[nt][1] = __expf(sf[nt][1]);
        sf[nt][2] = __expf(sf[nt][2]);
        sf[nt][3] = __expf(sf[nt][3]);
        lsum0 += sf[nt][0] + sf[nt][1];
        lsum1 += sf[nt][2] + sf[nt][3];
    }

#pragma unroll
    for (int j = 0; j < 2; j++) {
        if (2 * j < C2MAX) {
            const unsigned qoff = ((((unsigned)(j << 2)) | (unsigned)t) ^ xr) << 4;
            uint4 vb[8];
#pragma unroll
            for (int nt = 0; nt < 8; nt++)
                vb[nt] = *reinterpret_cast<const uint4*>(Vs + (nt * 8 + g) * 128 + qoff);
#pragma unroll
            for (int s2 = 0; s2 < 2; s2++) {
                if (2 * j + s2 < C2MAX) {
                    const int np = j * 4 + s2 * 2;
                    unsigned a0 = h2u(sf[np][0],     sf[np][1]);
                    unsigned a1 = h2u(sf[np][2],     sf[np][3]);
                    unsigned a2 = h2u(sf[np + 1][0], sf[np + 1][1]);
                    unsigned a3 = h2u(sf[np + 1][2], sf[np + 1][3]);
#pragma unroll
                    for (int nt = 0; nt < 8; nt++)
                        mma_f16(o[nt], a0, a1, a2, a3,
                                s2 ? vb[nt].z : vb[nt].x,
                                s2 ? vb[nt].w : vb[nt].y);
                }
            }
        }
    }
}

// ---------------------------------------------------------------------------
// fp16 tensor-core flash attention (R14 winner, unchanged): max-free softmax,
// clean main loop, peeled compile-time diagonal tile.
// ---------------------------------------------------------------------------
#define AST_K_BYTES (64 * 128)
#define AST_STAGE (2 * AST_K_BYTES)          // 16KB
#define ATTN_SMEM (2 * AST_STAGE)            // 32KB

__global__ void __launch_bounds__(128, 3)
attn_f16_kernel(const __half* __restrict__ qhg, const __half* __restrict__ khg,
                const __half* __restrict__ vtg, __half* __restrict__ yp) {
    extern __shared__ __align__(16) char smb[];
    const unsigned sbase = smem_to_u32(smb);

    const int tid = threadIdx.x;
    const int wid = tid >> 5;
    const int lane = tid & 31;
    const int g = lane >> 2;
    const int t = lane & 3;
    const int qi = (gridDim.x - 1) - blockIdx.x;   // heavy tiles first
    const int h = blockIdx.y;
    const int b = blockIdx.z;
    const int q0 = qi * 64;
    const size_t row_base = (size_t)b * T_;
    const int bh = b * H_ + h;
    const unsigned xr = (g & 1) << 2;

    uint4 qa[2][2];
#pragma unroll
    for (int j = 0; j < 2; j++) {
        const char* qp = reinterpret_cast<const char*>(qhg)
            + (row_base + q0 + wid * 16 + g) * 2048 + h * 128
            + ((((unsigned)(j << 2) | (unsigned)t) ^ xr) << 4);
        qa[j][0] = *reinterpret_cast<const uint4*>(qp);
        qa[j][1] = *reinterpret_cast<const uint4*>(qp + 8 * 2048);
    }

    float lsum0 = 0.0f, lsum1 = 0.0f;
    float o[8][4];
#pragma unroll
    for (int nt = 0; nt < 8; nt++)
#pragma unroll
        for (int r = 0; r < 4; r++) o[nt][r] = 0.0f;

    const char* khb = reinterpret_cast<const char*>(khg);
    const char* vtb = reinterpret_cast<const char*>(vtg);

    auto issue = [&](int kt) {
        const unsigned st = sbase + (unsigned)((kt & 1) * AST_STAGE);
        const int k0 = kt * 64;
#pragma unroll
        for (int i = 0; i < 4; i++) {
            int idx = i * 128 + tid;
            int kk = idx >> 3;
            int u = idx & 7;
            CP_ASYNC16(st + kk * 128 + u * 16,
                       khb + (row_base + k0 + kk) * 2048 + h * 128 + u * 16);
        }
#pragma unroll
        for (int i = 0; i < 4; i++) {
            int idx = i * 128 + tid;
            int d = idx >> 3;
            int u = idx & 7;
            CP_ASYNC16(st + AST_K_BYTES + d * 128 + u * 16,
                       vtb + (size_t)(bh * 64 + d) * 4096 + (size_t)kt * 128 + u * 16);
        }
        asm volatile("cp.async.commit_group;" ::: "memory");
    };

    issue(0);

    for (int kt = 0; kt < qi; kt++) {
        __syncthreads();
        issue(kt + 1);
        asm volatile("cp.async.wait_group 1;" ::: "memory");
        __syncthreads();

        const char* Ks = smb + (kt & 1) * AST_STAGE;
        const char* Vs = Ks + AST_K_BYTES;

        float sf[8][4];
#pragma unroll
        for (int nt = 0; nt < 8; nt++)
#pragma unroll
            for (int r = 0; r < 4; r++) sf[nt][r] = 0.0f;

#pragma unroll
        for (int j = 0; j < 2; j++) {
            const unsigned qoff = ((((unsigned)(j << 2)) | (unsigned)t) ^ xr) << 4;
            uint4 kb[8];
#pragma unroll
            for (int nt = 0; nt < 8; nt++)
                kb[nt] = *reinterpret_cast<const uint4*>(Ks + (nt * 8 + g) * 128 + qoff);
#pragma unroll
            for (int nt = 0; nt < 8; nt++)
                mma_f16(sf[nt],
                        qa[j][0].x, qa[j][1].x, qa[j][0].y, qa[j][1].y,
                        kb[nt].x, kb[nt].y);
#pragma unroll
            for (int nt = 0; nt < 8; nt++)
                mma_f16(sf[nt],
                        qa[j][0].z, qa[j][1].z, qa[j][0].w, qa[j][1].w,
                        kb[nt].z, kb[nt].w);
        }

#pragma unroll
        for (int nt = 0; nt < 8; nt++) {
            sf[nt][0] = __expf(sf[nt][0]);
            sf[nt][1] = __expf(sf[nt][1]);
            sf[nt][2] = __expf(sf[nt][2]);
            sf[nt][3] = __expf(sf[nt][3]);
            lsum0 += sf[nt][0] + sf[nt][1];
            lsum1 += sf[nt][2] + sf[nt][3];
        }

#pragma unroll
        for (int j = 0; j < 2; j++) {
            const unsigned qoff = ((((unsigned)(j << 2)) | (unsigned)t) ^ xr) << 4;
            uint4 vb[8];
#pragma unroll
            for (int nt = 0; nt < 8; nt++)
                vb[nt] = *reinterpret_cast<const uint4*>(Vs + (nt * 8 + g) * 128 + qoff);
#pragma unroll
            for (int s2 = 0; s2 < 2; s2++) {
                const int np = j * 4 + s2 * 2;
                unsigned a0 = h2u(sf[np][0],     sf[np][1]);
                unsigned a1 = h2u(sf[np][2],     sf[np][3]);
                unsigned a2 = h2u(sf[np + 1][0], sf[np + 1][1]);
                unsigned a3 = h2u(sf[np + 1][2], sf[np + 1][3]);
#pragma unroll
                for (int nt = 0; nt < 8; nt++)
                    mma_f16(o[nt], a0, a1, a2, a3,
                            s2 ? vb[nt].z : vb[nt].x,
                            s2 ? vb[nt].w : vb[nt].y);
            }
        }
    }

    // ---- Peeled diagonal tile ----
    {
        __syncthreads();
        asm volatile("cp.async.wait_group 0;" ::: "memory");
        __syncthreads();

        const char* Ks = smb + (qi & 1) * AST_STAGE;
        const char* Vs = Ks + AST_K_BYTES;
        const int k0 = qi * 64;
        const int qr0 = q0 + wid * 16 + g;

        switch (wid) {
        case 0: diag_tile<2, 1>(Ks, Vs, k0, qr0, qa, xr, g, t, o, lsum0, lsum1); break;
        case 1: diag_tile<4, 2>(Ks, Vs, k0, qr0, qa, xr, g, t, o, lsum0, lsum1); break;
        case 2: diag_tile<6, 3>(Ks, Vs, k0, qr0, qa, xr, g, t, o, lsum0, lsum1); break;
        default: diag_tile<8, 4>(Ks, Vs, k0, qr0, qa, xr, g, t, o, lsum0, lsum1); break;
        }
    }

    // ---- Epilogue ----
    lsum0 += __shfl_xor_sync(0xffffffffu, lsum0, 1);
    lsum0 += __shfl_xor_sync(0xffffffffu, lsum0, 2);
    lsum1 += __shfl_xor_sync(0xffffffffu, lsum1, 1);
    lsum1 += __shfl_xor_sync(0xffffffffu, lsum1, 2);
    const float il0 = 1.0f / lsum0;
    const float il1 = 1.0f / lsum1;

    char* ypc = reinterpret_cast<char*>(yp);
    const int hcol = h * D_;
    const int r0 = (int)(row_base + q0 + wid * 16 + g);
#pragma unroll
    for (int nt = 0; nt < 8; nt++) {
        const int col = hcol + nt * 8 + 2 * t;
        size_t off = qk_off(r0, col);
        __half2 hv0 = __floats2half2_rn(o[nt][0] * il0, o[nt][1] * il0);
        __half2 hv1 = __floats2half2_rn(o[nt][2] * il1, o[nt][3] * il1);
        *reinterpret_cast<__half2*>(ypc + off) = hv0;
        *reinterpret_cast<__half2*>(ypc + off + 8 * 2048) = hv1;
    }
}

// ---------------------------------------------------------------------------
// Launch
// ---------------------------------------------------------------------------
extern "C" void kernel_launch(void* const* d_in, const int* in_sizes, int n_in,
                              void* d_out, int out_size) {
    const float* x      = (const float*)d_in[0];   // [4,2048,1024]
    const float* W_attn = (const float*)d_in[1];   // [1024,3072]
    const float* W_proj = (const float*)d_in[2];   // [1024,1024]
    float* out = (float*)d_out;

    __half *xp, *yp, *wap, *wpp, *qh, *kh, *vt;
    cudaGetSymbolAddress((void**)&xp, g_xp);
    cudaGetSymbolAddress((void**)&yp, g_yp);
    cudaGetSymbolAddress((void**)&wap, g_wap);
    cudaGetSymbolAddress((void**)&wpp, g_wpp);
    cudaGetSymbolAddress((void**)&qh, g_qh);
    cudaGetSymbolAddress((void**)&kh, g_kh);
    cudaGetSymbolAddress((void**)&vt, g_vt);

    cudaFuncSetAttribute(gemm_f16_kernel,
                         cudaFuncAttributeMaxDynamicSharedMemorySize, FSMEM_BYTES);
    cudaFuncSetAttribute(attn_f16_kernel,
                         cudaFuncAttributeMaxDynamicSharedMemorySize, ATTN_SMEM);

    // 0) fused prep: x + both weights, one launch
    prep_fused_kernel<<<PREP_TOTAL, 256>>>(x, W_attn, W_proj, xp, wap, wpp);

    // 1) qkv = x @ W_attn -> Q (scaled), K, V^T directly as fp16 quad
    gemm_f16_kernel<<<dim3(C3_ / 128, M_ / 128), 128, FSMEM_BYTES>>>(
        xp, wap, nullptr, M_, C3_, C_, 1, qh, kh, vt);

    // 2) causal attention (fp16 mma, max-free softmax, peeled diag tile)
    attn_f16_kernel<<<dim3(T_ / 64, H_, B_), 128, ATTN_SMEM>>>(qh, kh, vt, yp);

    // 3) out = y @ W_proj (fp32-accum, fp32 out)
    gemm_f16_kernel<<<dim3(C_ / 128, M_ / 128), 128, FSMEM_BYTES>>>(
        yp, wpp, out, M_, C_, C_, 0, nullptr, nullptr, nullptr);
}